// round 11
// baseline (speedup 1.0000x reference)
#include <cuda_runtime.h>
#include <cuda_fp16.h>
#include <cstdint>
#include <math_constants.h>

// MiniRocket via mma.sync (HMMA) fp16 GEMM, round 11.
// R11: persistent CTAs + atomic work queue (grid 608 = 4 x 152 SM) to kill the
// 2.16->3 wave quantization tail of the 1280-CTA launch. Per-item body = R10:
// warp tile 32j x 32t, K=112 fp16, 7 ksteps, 3-stage cp.async ring, 4 CTAs/SM.

#define LSEQ    5000
#define PADX    2112
#define ROWLEN  9224            // PADX + LSEQ + PADX
#define NCH     12
#define NROWS   192             // 16 batch * 12 ch
#define NCHUNK  157             // ceil(5000/32)
#define ASTRIDE 240             // A row stride bytes (112 fp16 + pad), 16 | 240
#define NITEMS  1280            // 8 jt x 16 b x 10 di

#define BSZ     7168            // 56 rows x 128B per stage
#define SMEMSZ  30720           // A staging region (128*240) covers all stages

typedef unsigned u32;

// fp16 x, 8 shifted padded copies: g_xh[s*NROWS + row][p] = x[row][p + s - PADX]
__device__ __align__(16) __half g_xh[8 * NROWS * ROWLEN];
__device__ u32 g_work;

// ---------------- prep: padded fp16, 8 shifts; reset work queue ----------------
__global__ void prep_kernel(const float* __restrict__ x) {
    if (blockIdx.x == 0 && blockIdx.y == 0 && blockIdx.z == 0 && threadIdx.x == 0)
        g_work = 0;
    int p2 = blockIdx.x * 256 + threadIdx.x;
    if (p2 >= ROWLEN / 2) return;
    int row = blockIdx.y;                      // 0..191
    int s   = blockIdx.z;                      // 0..7
    int p   = p2 * 2;

    float v0 = 0.f, v1 = 0.f;
    int i0 = p + s - PADX, i1 = i0 + 1;
    if (i0 >= 0 && i0 < LSEQ) v0 = x[(size_t)row * LSEQ + i0];
    if (i1 >= 0 && i1 < LSEQ) v1 = x[(size_t)row * LSEQ + i1];

    __half2 h;
    h.x = __float2half(v0);
    h.y = __float2half(v1);
    *reinterpret_cast<__half2*>(g_xh + ((size_t)s * NROWS + row) * ROWLEN + p) = h;
}

// ---------------- PTX helpers (baseline, sm_80+) ----------------
__device__ __forceinline__ u32 smem_u32(const void* p) {
    u32 a;
    asm("{ .reg .u64 t; cvta.to.shared.u64 t, %1; cvt.u32.u64 %0, t; }"
        : "=r"(a) : "l"(p));
    return a;
}
__device__ __forceinline__ void ldsm_x4(u32& r0, u32& r1, u32& r2, u32& r3, u32 a) {
    asm volatile("ldmatrix.sync.aligned.m8n8.x4.shared.b16 {%0,%1,%2,%3}, [%4];"
                 : "=r"(r0), "=r"(r1), "=r"(r2), "=r"(r3) : "r"(a));
}
__device__ __forceinline__ void ldsm_x4t(u32& r0, u32& r1, u32& r2, u32& r3, u32 a) {
    asm volatile("ldmatrix.sync.aligned.m8n8.x4.trans.shared.b16 {%0,%1,%2,%3}, [%4];"
                 : "=r"(r0), "=r"(r1), "=r"(r2), "=r"(r3) : "r"(a));
}
__device__ __forceinline__ void mma16816(float* d, const u32* a, u32 b0, u32 b1) {
    asm volatile(
        "mma.sync.aligned.m16n8k16.row.col.f32.f16.f16.f32 "
        "{%0,%1,%2,%3}, {%4,%5,%6,%7}, {%8,%9}, {%0,%1,%2,%3};"
        : "+f"(d[0]), "+f"(d[1]), "+f"(d[2]), "+f"(d[3])
        : "r"(a[0]), "r"(a[1]), "r"(a[2]), "r"(a[3]), "r"(b0), "r"(b1));
}
__device__ __forceinline__ void cp16(u32 dst, const void* src) {
    asm volatile("cp.async.cg.shared.global [%0], [%1], 16;"
                 :: "r"(dst), "l"(src) : "memory");
}
#define CP_COMMIT() asm volatile("cp.async.commit_group;" ::: "memory")
#define CP_WAIT(n)  asm volatile("cp.async.wait_group %0;" :: "n"(n) : "memory")

// ---------------- main kernel (persistent) ----------------
__global__ void __launch_bounds__(128, 4)
mr_hmma(const float* __restrict__ W, const float* __restrict__ bias,
        float* __restrict__ out)
{
    extern __shared__ __align__(1024) char smem[];
    __shared__ u32 s_item;
    const u32 sb = smem_u32(smem);
    const int tid  = threadIdx.x;
    const int wid  = tid >> 5;      // 0..3
    const int lane = tid & 31;
    const __half* gx = g_xh;

    for (;;) {
        if (tid == 0) s_item = atomicAdd(&g_work, 1u);
        __syncthreads();
        const u32 item = s_item;
        if (item >= NITEMS) break;

        const int jt = item & 7;            // 0..7
        const int b  = (item >> 3) & 15;    // 0..15
        const int di = item >> 7;           // 0..9
        const int d  = 1 << di;

        // ---- stage A [128 j x 112 K] fp16 (overlaid on stages; used once) ----
        for (int e = tid; e < 128 * 56; e += 128) {
            int j  = e / 56;
            int kk = (e - j * 56) * 2;
            u32 val = 0;
            int jg = jt * 128 + j;
            if (jg < 1000 && kk < 108) {
                float2 w2 = *reinterpret_cast<const float2*>(
                    W + (size_t)(di * 1000 + jg) * 108 + kk);
                __half2 h;
                h.x = __float2half(w2.x);
                h.y = __float2half(w2.y);
                val = *reinterpret_cast<u32*>(&h);
            }
            *reinterpret_cast<u32*>(smem + j * ASTRIDE + kk * 2) = val;
        }
        __syncthreads();

        // ---- A fragments: 7 ksteps x 2 mtiles x 4 regs ----
        u32 afr[7][2][4];
#pragma unroll
        for (int mt = 0; mt < 2; mt++) {
            u32 abase = sb + (u32)(wid * 32 + mt * 16 + (lane & 15)) * ASTRIDE
                      + (u32)(lane >> 4) * 16;
#pragma unroll
            for (int q = 0; q < 7; q++)
                ldsm_x4(afr[q][mt][0], afr[q][mt][1], afr[q][mt][2], afr[q][mt][3],
                        abase + q * 32);
        }
        __syncthreads();   // frags loaded before stage buffers are written

        // ---- staging descriptors: 4 slots/thread ----
        u32 so[4];  // element offset into g_xh (advanced by 32 per chunk)
        u32 sd[4];  // swizzled smem byte offset (~0 = invalid)
#pragma unroll
        for (int sx = 0; sx < 4; sx++) {
            int e = tid + (sx << 7);
            bool valid = e < 108 * 4;
            int s  = valid ? (e >> 2) : 0;
            int ch = e & 3;
            int c = s / 9, k = s - c * 9;
            int o0 = PADX + (k - 4) * d + ch * 8;
            int s8 = o0 & 7, p0 = o0 - s8;
            so[sx] = (u32)((s8 * NROWS + b * NCH + c) * ROWLEN + p0);
            int u = s >> 1, half = s & 1;
            u32 off = (u32)u * 128u + ((u32)((half * 4 + ch) ^ (u & 7)) * 16u);
            sd[sx] = valid ? off : 0xFFFFFFFFu;
        }

        // ---- zero pad slots 108..111 in all 3 stages (A staging clobbered) ----
        if (tid < 48) {
            int st = tid >> 4, idx = tid & 15;
            int s = 108 + (idx >> 2), ch = idx & 3;
            int u = s >> 1, half = s & 1;
            u32 off = (u32)u * 128u + ((u32)((half * 4 + ch) ^ (u & 7)) * 16u);
            *reinterpret_cast<uint4*>(smem + st * BSZ + off) = make_uint4(0, 0, 0, 0);
        }

        // ---- prologue: async-stage chunks 0 and 1 ----
#pragma unroll
        for (int sx = 0; sx < 4; sx++)
            if (sd[sx] != 0xFFFFFFFFu) cp16(sb + 0 * BSZ + sd[sx], gx + so[sx]);
        CP_COMMIT();
#pragma unroll
        for (int sx = 0; sx < 4; sx++)
            if (sd[sx] != 0xFFFFFFFFu) cp16(sb + 1 * BSZ + sd[sx], gx + so[sx] + 32u);
        CP_COMMIT();

        // ---- per-lane ldsm-B address components ----
        const u32 laneU    = (u32)((lane & 15) >> 1);
        const u32 laneHalf = (u32)(lane & 1);
        const u32 g0       = (u32)(lane >> 4);
        const u32 laneBase = laneU * 128u;
        u32 xvo[2];
#pragma unroll
        for (int p = 0; p < 2; p++)
            xvo[p] = ((laneHalf * 4u + g0 + 2u * (u32)p) ^ laneU) * 16u;

        // ---- epilogue state: lane owns 4 j rows ----
        const int qd  = lane >> 2;
        const int j0w = jt * 128 + wid * 32;
        int jr[4] = { j0w + qd, j0w + qd + 8, j0w + 16 + qd, j0w + 24 + qd };
        float bv[4], m[4];
        int   cn[4];
#pragma unroll
        for (int r = 0; r < 4; r++) {
            bv[r] = (jr[r] < 1000) ? bias[di * 1000 + jr[r]] : 0.0f;
            m[r]  = -CUDART_INF_F;
            cn[r] = 0;
        }

        int cur = 0;          // stage holding chunk i
        int wr  = 2;          // stage to write chunk i+2 into
        u32 eoff = 64;        // element offset of chunk i+2

        for (int i = 0; i < NCHUNK; i++) {
            CP_WAIT(1);            // chunk i resident
            __syncthreads();       // visible to all; stage 'wr' drained

            if (i + 2 < NCHUNK) {
                const u32 bw = sb + (u32)wr * BSZ;
#pragma unroll
                for (int sx = 0; sx < 4; sx++)
                    if (sd[sx] != 0xFFFFFFFFu)
                        cp16(bw + sd[sx], gx + so[sx] + eoff);
            }
            CP_COMMIT();
            eoff += 32;

            // MMA chunk i: D[32j x 32t] per warp, 7 ksteps
            float dacc[2][4][4];
#pragma unroll
            for (int mt = 0; mt < 2; mt++)
#pragma unroll
                for (int n = 0; n < 4; n++)
#pragma unroll
                    for (int r = 0; r < 4; r++) dacc[mt][n][r] = 0.f;

            const u32 bb = sb + (u32)cur * BSZ + laneBase;
#pragma unroll
            for (int q = 0; q < 7; q++) {
#pragma unroll
                for (int p = 0; p < 2; p++) {
                    u32 b0, b1, b2, b3;
                    ldsm_x4t(b0, b1, b2, b3, bb + (u32)q * 1024u + xvo[p]);
                    mma16816(dacc[0][2 * p],     afr[q][0], b0, b1);
                    mma16816(dacc[0][2 * p + 1], afr[q][0], b2, b3);
                    mma16816(dacc[1][2 * p],     afr[q][1], b0, b1);
                    mma16816(dacc[1][2 * p + 1], afr[q][1], b2, b3);
                }
            }

            // fused epilogue (last chunk: only t 0..7 valid -> ntile 0)
            const int ntmax = (i == NCHUNK - 1) ? 1 : 4;
#pragma unroll
            for (int n = 0; n < 4; n++) {
                if (n < ntmax) {
#pragma unroll
                    for (int mt = 0; mt < 2; mt++) {
                        m[2 * mt]     = fmaxf(m[2 * mt],
                                              fmaxf(dacc[mt][n][0], dacc[mt][n][1]));
                        cn[2 * mt]   += (dacc[mt][n][0] > bv[2 * mt])
                                      + (dacc[mt][n][1] > bv[2 * mt]);
                        m[2 * mt + 1] = fmaxf(m[2 * mt + 1],
                                              fmaxf(dacc[mt][n][2], dacc[mt][n][3]));
                        cn[2 * mt + 1] += (dacc[mt][n][2] > bv[2 * mt + 1])
                                        + (dacc[mt][n][3] > bv[2 * mt + 1]);
                    }
                }
            }

            cur = (cur == 2) ? 0 : cur + 1;
            wr  = (wr  == 2) ? 0 : wr  + 1;
        }

        // ---- reduce across the 4 lanes of each quad, write out ----
#pragma unroll
        for (int o = 1; o < 4; o <<= 1) {
#pragma unroll
            for (int r = 0; r < 4; r++) {
                m[r]  = fmaxf(m[r], __shfl_xor_sync(0xffffffffu, m[r], o));
                cn[r] += __shfl_xor_sync(0xffffffffu, cn[r], o);
            }
        }
        if ((lane & 3) == 0) {
            float* ob = out + (size_t)b * 20000 + di * 2000;
#pragma unroll
            for (int r = 0; r < 4; r++) {
                if (jr[r] < 1000) {
                    ob[jr[r]]        = m[r];
                    ob[1000 + jr[r]] = (float)cn[r] * (1.0f / LSEQ);
                }
            }
        }

        // drain async queue before next item's A staging overwrites stages
        CP_WAIT(0);
        __syncthreads();
    }
}

extern "C" void kernel_launch(void* const* d_in, const int* in_sizes, int n_in,
                              void* d_out, int out_size)
{
    const float* x    = (const float*)d_in[0];  // [16,12,5000]
    const float* W    = (const float*)d_in[1];  // [10,1000,12,9]
    const float* bias = (const float*)d_in[2];  // [10,1000]
    float* out = (float*)d_out;                 // [16,20000]

    dim3 pg((ROWLEN / 2 + 255) / 256, NROWS, 8);
    prep_kernel<<<pg, 256>>>(x);

    cudaFuncSetAttribute(mr_hmma, cudaFuncAttributeMaxDynamicSharedMemorySize, SMEMSZ);
    mr_hmma<<<608, 128, SMEMSZ>>>(W, bias, out);
}

// round 12
// speedup vs baseline: 1.0902x; 1.0902x over previous
#include <cuda_runtime.h>
#include <cuda_fp16.h>
#include <cstdint>
#include <math_constants.h>

// MiniRocket via mma.sync (HMMA) fp16 GEMM, round 12.
// R12 = R10 (best, 496us) + chunk-PAIR main loop on a 6-stage cp.async ring:
// one sync / one commit / one wait per 64 t (was per 32 t), branch-free hot
// loop (chunks 0..155 all-full; chunk 156 handled as a tail block).
// Warp tile 32j x 32t, K=112 fp16, 7 ksteps, 4 CTAs/SM, grid 1280.

#define LSEQ    5000
#define PADX    2112
#define ROWLEN  9224            // PADX + LSEQ + PADX
#define NCH     12
#define NROWS   192             // 16 batch * 12 ch
#define NPAIR   78              // pairs of full chunks (0..155)
#define ASTRIDE 240             // A row stride bytes (112 fp16 + pad), 16 | 240

#define BSZ     7168            // 56 rows x 128B per stage (one 32-t chunk)
#define NSTAGE  6
#define SMEMSZ  (NSTAGE * BSZ)  // 43008; A staging (30720) overlaid on stages

typedef unsigned u32;

// fp16 x, 8 shifted padded copies: g_xh[s*NROWS + row][p] = x[row][p + s - PADX]
__device__ __align__(16) __half g_xh[8 * NROWS * ROWLEN];

// ---------------- prep: padded fp16, 8 shifts ----------------
__global__ void prep_kernel(const float* __restrict__ x) {
    int p2 = blockIdx.x * 256 + threadIdx.x;
    if (p2 >= ROWLEN / 2) return;
    int row = blockIdx.y;                      // 0..191
    int s   = blockIdx.z;                      // 0..7
    int p   = p2 * 2;

    float v0 = 0.f, v1 = 0.f;
    int i0 = p + s - PADX, i1 = i0 + 1;
    if (i0 >= 0 && i0 < LSEQ) v0 = x[(size_t)row * LSEQ + i0];
    if (i1 >= 0 && i1 < LSEQ) v1 = x[(size_t)row * LSEQ + i1];

    __half2 h;
    h.x = __float2half(v0);
    h.y = __float2half(v1);
    *reinterpret_cast<__half2*>(g_xh + ((size_t)s * NROWS + row) * ROWLEN + p) = h;
}

// ---------------- PTX helpers (baseline, sm_80+) ----------------
__device__ __forceinline__ u32 smem_u32(const void* p) {
    u32 a;
    asm("{ .reg .u64 t; cvta.to.shared.u64 t, %1; cvt.u32.u64 %0, t; }"
        : "=r"(a) : "l"(p));
    return a;
}
__device__ __forceinline__ void ldsm_x4(u32& r0, u32& r1, u32& r2, u32& r3, u32 a) {
    asm volatile("ldmatrix.sync.aligned.m8n8.x4.shared.b16 {%0,%1,%2,%3}, [%4];"
                 : "=r"(r0), "=r"(r1), "=r"(r2), "=r"(r3) : "r"(a));
}
__device__ __forceinline__ void ldsm_x4t(u32& r0, u32& r1, u32& r2, u32& r3, u32 a) {
    asm volatile("ldmatrix.sync.aligned.m8n8.x4.trans.shared.b16 {%0,%1,%2,%3}, [%4];"
                 : "=r"(r0), "=r"(r1), "=r"(r2), "=r"(r3) : "r"(a));
}
__device__ __forceinline__ void mma16816(float* d, const u32* a, u32 b0, u32 b1) {
    asm volatile(
        "mma.sync.aligned.m16n8k16.row.col.f32.f16.f16.f32 "
        "{%0,%1,%2,%3}, {%4,%5,%6,%7}, {%8,%9}, {%0,%1,%2,%3};"
        : "+f"(d[0]), "+f"(d[1]), "+f"(d[2]), "+f"(d[3])
        : "r"(a[0]), "r"(a[1]), "r"(a[2]), "r"(a[3]), "r"(b0), "r"(b1));
}
__device__ __forceinline__ void cp16(u32 dst, const void* src) {
    asm volatile("cp.async.cg.shared.global [%0], [%1], 16;"
                 :: "r"(dst), "l"(src) : "memory");
}
#define CP_COMMIT() asm volatile("cp.async.commit_group;" ::: "memory")
#define CP_WAIT(n)  asm volatile("cp.async.wait_group %0;" :: "n"(n) : "memory")

// ---------------- main kernel ----------------
__global__ void __launch_bounds__(128, 4)
mr_hmma(const float* __restrict__ W, const float* __restrict__ bias,
        float* __restrict__ out)
{
    extern __shared__ __align__(1024) char smem[];
    const u32 sb = smem_u32(smem);
    const int tid  = threadIdx.x;
    const int wid  = tid >> 5;      // 0..3
    const int lane = tid & 31;

    const int jt = blockIdx.x;      // 0..7
    const int b  = blockIdx.y;      // 0..15
    const int di = blockIdx.z;      // 0..9
    const int d  = 1 << di;

    // ---- stage A [128 j x 112 K] fp16 (overlaid on stages; used once) ----
    for (int e = tid; e < 128 * 56; e += 128) {
        int j  = e / 56;
        int kk = (e - j * 56) * 2;
        u32 val = 0;
        int jg = jt * 128 + j;
        if (jg < 1000 && kk < 108) {
            float2 w2 = *reinterpret_cast<const float2*>(
                W + (size_t)(di * 1000 + jg) * 108 + kk);
            __half2 h;
            h.x = __float2half(w2.x);
            h.y = __float2half(w2.y);
            val = *reinterpret_cast<u32*>(&h);
        }
        *reinterpret_cast<u32*>(smem + j * ASTRIDE + kk * 2) = val;
    }
    __syncthreads();

    // ---- A fragments: 7 ksteps x 2 mtiles x 4 regs ----
    u32 afr[7][2][4];
#pragma unroll
    for (int mt = 0; mt < 2; mt++) {
        u32 abase = sb + (u32)(wid * 32 + mt * 16 + (lane & 15)) * ASTRIDE
                  + (u32)(lane >> 4) * 16;
#pragma unroll
        for (int q = 0; q < 7; q++)
            ldsm_x4(afr[q][mt][0], afr[q][mt][1], afr[q][mt][2], afr[q][mt][3],
                    abase + q * 32);
    }
    __syncthreads();   // frags loaded before stage buffers are written

    // ---- staging descriptors: 4 slots/thread (432 valid of 512) ----
    u32 so[4];  // element offset into g_xh (advanced by 32 per chunk)
    u32 sd[4];  // swizzled smem byte offset (~0 = invalid)
#pragma unroll
    for (int sx = 0; sx < 4; sx++) {
        int e = tid + (sx << 7);
        bool valid = e < 108 * 4;
        int s  = valid ? (e >> 2) : 0;
        int ch = e & 3;
        int c = s / 9, k = s - c * 9;
        int o0 = PADX + (k - 4) * d + ch * 8;
        int s8 = o0 & 7, p0 = o0 - s8;
        so[sx] = (u32)((s8 * NROWS + b * NCH + c) * ROWLEN + p0);
        int u = s >> 1, half = s & 1;
        u32 off = (u32)u * 128u + ((u32)((half * 4 + ch) ^ (u & 7)) * 16u);
        sd[sx] = valid ? off : 0xFFFFFFFFu;
    }

    // ---- zero pad slots 108..111 in all 6 stages ----
    if (tid < 96) {
        int st = tid >> 4, idx = tid & 15;
        int s = 108 + (idx >> 2), ch = idx & 3;
        int u = s >> 1, half = s & 1;
        u32 off = (u32)u * 128u + ((u32)((half * 4 + ch) ^ (u & 7)) * 16u);
        *reinterpret_cast<uint4*>(smem + st * BSZ + off) = make_uint4(0, 0, 0, 0);
    }

    // ---- prologue: async-stage pairs 0 (chunks 0,1) and 1 (chunks 2,3) ----
    const __half* gx = g_xh;
#pragma unroll
    for (int sx = 0; sx < 4; sx++)
        if (sd[sx] != 0xFFFFFFFFu) {
            cp16(sb + 0 * BSZ + sd[sx], gx + so[sx]);
            cp16(sb + 1 * BSZ + sd[sx], gx + so[sx] + 32u);
        }
    CP_COMMIT();
#pragma unroll
    for (int sx = 0; sx < 4; sx++)
        if (sd[sx] != 0xFFFFFFFFu) {
            cp16(sb + 2 * BSZ + sd[sx], gx + so[sx] + 64u);
            cp16(sb + 3 * BSZ + sd[sx], gx + so[sx] + 96u);
        }
    CP_COMMIT();

    // ---- per-lane ldsm-B address components ----
    const u32 laneU    = (u32)((lane & 15) >> 1);
    const u32 laneHalf = (u32)(lane & 1);
    const u32 g0       = (u32)(lane >> 4);
    const u32 laneBase = laneU * 128u;
    u32 xvo[2];
#pragma unroll
    for (int p = 0; p < 2; p++)
        xvo[p] = ((laneHalf * 4u + g0 + 2u * (u32)p) ^ laneU) * 16u;

    // ---- epilogue state: lane owns 4 j rows ----
    const int qd  = lane >> 2;
    const int j0w = jt * 128 + wid * 32;
    int jr[4] = { j0w + qd, j0w + qd + 8, j0w + 16 + qd, j0w + 24 + qd };
    float bv[4], m[4];
    int   cn[4];
#pragma unroll
    for (int r = 0; r < 4; r++) {
        bv[r] = (jr[r] < 1000) ? bias[di * 1000 + jr[r]] : 0.0f;
        m[r]  = -CUDART_INF_F;
        cn[r] = 0;
    }

    // one 32-t sub-chunk: MMA from stage at byte offset 'soff', full epilogue
    auto subchunk = [&](u32 soff, int ntmax) {
        float dacc[2][4][4];
#pragma unroll
        for (int mt = 0; mt < 2; mt++)
#pragma unroll
            for (int n = 0; n < 4; n++)
#pragma unroll
                for (int r = 0; r < 4; r++) dacc[mt][n][r] = 0.f;

        const u32 bb = sb + soff + laneBase;
#pragma unroll
        for (int q = 0; q < 7; q++) {
#pragma unroll
            for (int p = 0; p < 2; p++) {
                u32 b0, b1, b2, b3;
                ldsm_x4t(b0, b1, b2, b3, bb + (u32)q * 1024u + xvo[p]);
                mma16816(dacc[0][2 * p],     afr[q][0], b0, b1);
                mma16816(dacc[0][2 * p + 1], afr[q][0], b2, b3);
                mma16816(dacc[1][2 * p],     afr[q][1], b0, b1);
                mma16816(dacc[1][2 * p + 1], afr[q][1], b2, b3);
            }
        }
#pragma unroll
        for (int n = 0; n < 4; n++) {
            if (n < ntmax) {
#pragma unroll
                for (int mt = 0; mt < 2; mt++) {
                    m[2 * mt]     = fmaxf(m[2 * mt],
                                          fmaxf(dacc[mt][n][0], dacc[mt][n][1]));
                    cn[2 * mt]   += (dacc[mt][n][0] > bv[2 * mt])
                                  + (dacc[mt][n][1] > bv[2 * mt]);
                    m[2 * mt + 1] = fmaxf(m[2 * mt + 1],
                                          fmaxf(dacc[mt][n][2], dacc[mt][n][3]));
                    cn[2 * mt + 1] += (dacc[mt][n][2] > bv[2 * mt + 1])
                                    + (dacc[mt][n][3] > bv[2 * mt + 1]);
                }
            }
        }
    };

    // ---- main loop: 78 pairs (chunks 0..155, all full) ----
    u32 cb = 0;                 // stage byte offset of first chunk of pair p
    u32 wb = 4 * BSZ;           // stage byte offset of first chunk of pair p+2
    u32 eoff = 128;             // element offset of pair p+2 (chunk 2p+4)

    for (int p = 0; p < NPAIR; p++) {
        CP_WAIT(1);             // pair p resident
        __syncthreads();        // visible; pair p+2's stages drained

        // issue pair p+2 (chunks 2p+4, 2p+5) — chunk 156 lands here at p=76
        if (p + 2 <= NPAIR) {   // chunks 2p+4 <= 156 exist; 157 clamps to 156
            const u32 c0 = (2 * p + 4 < 157) ? eoff : eoff;   // chunk 2p+4
#pragma unroll
            for (int sx = 0; sx < 4; sx++)
                if (sd[sx] != 0xFFFFFFFFu) {
                    cp16(wb + sb + sd[sx], gx + so[sx] + c0);
                    if (2 * p + 5 < 157)
                        cp16(wb + BSZ - ((wb + BSZ == NSTAGE * BSZ) ? NSTAGE * BSZ : 0)
                             + sb + sd[sx], gx + so[sx] + c0 + 32u);
                }
        }
        CP_COMMIT();
        eoff += 64;

        // compute pair p
        subchunk(cb, 4);
        subchunk(cb + BSZ, 4);

        cb += 2 * BSZ; if (cb >= NSTAGE * BSZ) cb -= NSTAGE * BSZ;
        wb += 2 * BSZ; if (wb >= NSTAGE * BSZ) wb -= NSTAGE * BSZ;
    }

    // ---- tail: chunk 156 (stage 156 % 6 = 0; only first 8 t valid) ----
    CP_WAIT(0);
    __syncthreads();
    subchunk((u32)((156 % NSTAGE) * BSZ), 1);

    // ---- reduce across the 4 lanes of each quad, write out ----
#pragma unroll
    for (int o = 1; o < 4; o <<= 1) {
#pragma unroll
        for (int r = 0; r < 4; r++) {
            m[r]  = fmaxf(m[r], __shfl_xor_sync(0xffffffffu, m[r], o));
            cn[r] += __shfl_xor_sync(0xffffffffu, cn[r], o);
        }
    }
    if ((lane & 3) == 0) {
        float* ob = out + (size_t)b * 20000 + di * 2000;
#pragma unroll
        for (int r = 0; r < 4; r++) {
            if (jr[r] < 1000) {
                ob[jr[r]]        = m[r];
                ob[1000 + jr[r]] = (float)cn[r] * (1.0f / LSEQ);
            }
        }
    }
}

extern "C" void kernel_launch(void* const* d_in, const int* in_sizes, int n_in,
                              void* d_out, int out_size)
{
    const float* x    = (const float*)d_in[0];  // [16,12,5000]
    const float* W    = (const float*)d_in[1];  // [10,1000,12,9]
    const float* bias = (const float*)d_in[2];  // [10,1000]
    float* out = (float*)d_out;                 // [16,20000]

    dim3 pg((ROWLEN / 2 + 255) / 256, NROWS, 8);
    prep_kernel<<<pg, 256>>>(x);

    cudaFuncSetAttribute(mr_hmma, cudaFuncAttributeMaxDynamicSharedMemorySize, SMEMSZ);
    dim3 grid(8, 16, 10);
    mr_hmma<<<grid, 128, SMEMSZ>>>(W, bias, out);
}

// round 13
// speedup vs baseline: 1.1005x; 1.0095x over previous
#include <cuda_runtime.h>
#include <cuda_fp16.h>
#include <cstdint>
#include <math_constants.h>

// MiniRocket via mma.sync (HMMA) fp16 GEMM, round 13.
// R13 = R10 + occupancy push: p-outer loop (dacc 32->16 regs) and A mt=1
// fragments reloaded per (p,q) from a persistent SMEM region (afr 56->28 regs)
// -> ~95 regs, __launch_bounds__(128,5): 5 CTAs/SM = 20 warps (was 16).
// Warp tile 32j x 32t, K=112 fp16, 7 ksteps, 3-stage cp.async ring, grid 1280.

#define LSEQ    5000
#define PADX    2112
#define ROWLEN  9224            // PADX + LSEQ + PADX
#define NCH     12
#define NROWS   192             // 16 batch * 12 ch
#define NCHUNK  157             // ceil(5000/32)
#define ASTRIDE 240             // A row stride bytes (112 fp16 + pad), 16 | 240

#define BSZ     7168            // 56 rows x 128B per stage
#define NSTAGE  3
#define A1OFF   (NSTAGE * BSZ)  // 21504: persistent A (mt=1, 64 rows x 240B)
#define SMEMSZ  (A1OFF + 64 * ASTRIDE)   // 36864 -> 5 CTAs/SM

typedef unsigned u32;

// fp16 x, 8 shifted padded copies: g_xh[s*NROWS + row][p] = x[row][p + s - PADX]
__device__ __align__(16) __half g_xh[8 * NROWS * ROWLEN];

// ---------------- prep: padded fp16, 8 shifts ----------------
__global__ void prep_kernel(const float* __restrict__ x) {
    int p2 = blockIdx.x * 256 + threadIdx.x;
    if (p2 >= ROWLEN / 2) return;
    int row = blockIdx.y;                      // 0..191
    int s   = blockIdx.z;                      // 0..7
    int p   = p2 * 2;

    float v0 = 0.f, v1 = 0.f;
    int i0 = p + s - PADX, i1 = i0 + 1;
    if (i0 >= 0 && i0 < LSEQ) v0 = x[(size_t)row * LSEQ + i0];
    if (i1 >= 0 && i1 < LSEQ) v1 = x[(size_t)row * LSEQ + i1];

    __half2 h;
    h.x = __float2half(v0);
    h.y = __float2half(v1);
    *reinterpret_cast<__half2*>(g_xh + ((size_t)s * NROWS + row) * ROWLEN + p) = h;
}

// ---------------- PTX helpers (baseline, sm_80+) ----------------
__device__ __forceinline__ u32 smem_u32(const void* p) {
    u32 a;
    asm("{ .reg .u64 t; cvta.to.shared.u64 t, %1; cvt.u32.u64 %0, t; }"
        : "=r"(a) : "l"(p));
    return a;
}
__device__ __forceinline__ void ldsm_x4(u32& r0, u32& r1, u32& r2, u32& r3, u32 a) {
    asm volatile("ldmatrix.sync.aligned.m8n8.x4.shared.b16 {%0,%1,%2,%3}, [%4];"
                 : "=r"(r0), "=r"(r1), "=r"(r2), "=r"(r3) : "r"(a));
}
__device__ __forceinline__ void ldsm_x4t(u32& r0, u32& r1, u32& r2, u32& r3, u32 a) {
    asm volatile("ldmatrix.sync.aligned.m8n8.x4.trans.shared.b16 {%0,%1,%2,%3}, [%4];"
                 : "=r"(r0), "=r"(r1), "=r"(r2), "=r"(r3) : "r"(a));
}
__device__ __forceinline__ void mma16816(float* d, const u32* a, u32 b0, u32 b1) {
    asm volatile(
        "mma.sync.aligned.m16n8k16.row.col.f32.f16.f16.f32 "
        "{%0,%1,%2,%3}, {%4,%5,%6,%7}, {%8,%9}, {%0,%1,%2,%3};"
        : "+f"(d[0]), "+f"(d[1]), "+f"(d[2]), "+f"(d[3])
        : "r"(a[0]), "r"(a[1]), "r"(a[2]), "r"(a[3]), "r"(b0), "r"(b1));
}
__device__ __forceinline__ void cp16(u32 dst, const void* src) {
    asm volatile("cp.async.cg.shared.global [%0], [%1], 16;"
                 :: "r"(dst), "l"(src) : "memory");
}
#define CP_COMMIT() asm volatile("cp.async.commit_group;" ::: "memory")
#define CP_WAIT(n)  asm volatile("cp.async.wait_group %0;" :: "n"(n) : "memory")

// ---------------- main kernel ----------------
__global__ void __launch_bounds__(128, 5)
mr_hmma(const float* __restrict__ W, const float* __restrict__ bias,
        float* __restrict__ out)
{
    extern __shared__ __align__(1024) char smem[];
    const u32 sb = smem_u32(smem);
    const int tid  = threadIdx.x;
    const int wid  = tid >> 5;      // 0..3
    const int lane = tid & 31;

    const int jt = blockIdx.x;      // 0..7
    const int b  = blockIdx.y;      // 0..15
    const int di = blockIdx.z;      // 0..9
    const int d  = 1 << di;

    // ---- stage A [128 j x 112 K] fp16: mt=0 rows (j&16==0) into scratch
    //      at offset 0 (transient), mt=1 rows into persistent A1 region ----
    for (int e = tid; e < 128 * 56; e += 128) {
        int j  = e / 56;
        int kk = (e - j * 56) * 2;
        u32 val = 0;
        int jg = jt * 128 + j;
        if (jg < 1000 && kk < 108) {
            float2 w2 = *reinterpret_cast<const float2*>(
                W + (size_t)(di * 1000 + jg) * 108 + kk);
            __half2 h;
            h.x = __float2half(w2.x);
            h.y = __float2half(w2.y);
            val = *reinterpret_cast<u32*>(&h);
        }
        u32 slot = (u32)((j >> 5) * 16 + (j & 15));
        u32 base = (j & 16) ? (u32)A1OFF : 0u;
        *reinterpret_cast<u32*>(smem + base + slot * ASTRIDE + kk * 2) = val;
    }
    __syncthreads();

    // ---- A mt=0 fragments -> registers (7 ksteps x 4 regs = 28) ----
    u32 afr[7][4];
    {
        u32 abase = sb + (u32)(wid * 16 + (lane & 15)) * ASTRIDE
                  + (u32)(lane >> 4) * 16;
#pragma unroll
        for (int q = 0; q < 7; q++)
            ldsm_x4(afr[q][0], afr[q][1], afr[q][2], afr[q][3], abase + q * 32);
    }
    const u32 a1base = sb + (u32)A1OFF
                     + (u32)(wid * 16 + (lane & 15)) * ASTRIDE
                     + (u32)(lane >> 4) * 16;
    __syncthreads();   // mt=0 frags loaded before stage buffers overwrite scratch

    // ---- staging descriptors: 4 slots/thread (432 valid of 512) ----
    u32 so[4];  // element offset into g_xh (advanced by 32 per chunk)
    u32 sd[4];  // swizzled smem byte offset (~0 = invalid)
#pragma unroll
    for (int sx = 0; sx < 4; sx++) {
        int e = tid + (sx << 7);
        bool valid = e < 108 * 4;
        int s  = valid ? (e >> 2) : 0;
        int ch = e & 3;
        int c = s / 9, k = s - c * 9;
        int o0 = PADX + (k - 4) * d + ch * 8;
        int s8 = o0 & 7, p0 = o0 - s8;
        so[sx] = (u32)((s8 * NROWS + b * NCH + c) * ROWLEN + p0);
        int u = s >> 1, half = s & 1;
        u32 off = (u32)u * 128u + ((u32)((half * 4 + ch) ^ (u & 7)) * 16u);
        sd[sx] = valid ? off : 0xFFFFFFFFu;
    }

    // ---- zero pad slots 108..111 in all 3 stages ----
    if (tid < 48) {
        int st = tid >> 4, idx = tid & 15;
        int s = 108 + (idx >> 2), ch = idx & 3;
        int u = s >> 1, half = s & 1;
        u32 off = (u32)u * 128u + ((u32)((half * 4 + ch) ^ (u & 7)) * 16u);
        *reinterpret_cast<uint4*>(smem + st * BSZ + off) = make_uint4(0, 0, 0, 0);
    }

    // ---- prologue: async-stage chunks 0 and 1 ----
    const __half* gx = g_xh;
#pragma unroll
    for (int sx = 0; sx < 4; sx++)
        if (sd[sx] != 0xFFFFFFFFu) cp16(sb + 0 * BSZ + sd[sx], gx + so[sx]);
    CP_COMMIT();
#pragma unroll
    for (int sx = 0; sx < 4; sx++)
        if (sd[sx] != 0xFFFFFFFFu) cp16(sb + 1 * BSZ + sd[sx], gx + so[sx] + 32u);
    CP_COMMIT();

    // ---- per-lane ldsm-B address components ----
    const u32 laneU    = (u32)((lane & 15) >> 1);
    const u32 laneHalf = (u32)(lane & 1);
    const u32 g0       = (u32)(lane >> 4);
    const u32 laneBase = laneU * 128u;
    u32 xvo[2];
#pragma unroll
    for (int p = 0; p < 2; p++)
        xvo[p] = ((laneHalf * 4u + g0 + 2u * (u32)p) ^ laneU) * 16u;

    // ---- epilogue state: lane owns 4 j rows ----
    const int qd  = lane >> 2;
    const int j0w = jt * 128 + wid * 32;
    int jr[4] = { j0w + qd, j0w + qd + 8, j0w + 16 + qd, j0w + 24 + qd };
    float bv[4], m[4];
    int   cn[4];
#pragma unroll
    for (int r = 0; r < 4; r++) {
        bv[r] = (jr[r] < 1000) ? bias[di * 1000 + jr[r]] : 0.0f;
        m[r]  = -CUDART_INF_F;
        cn[r] = 0;
    }

    int cur = 0;          // stage holding chunk i
    int wr  = 2;          // stage to write chunk i+2 into
    u32 eoff = 64;        // element offset of chunk i+2

    for (int i = 0; i < NCHUNK; i++) {
        CP_WAIT(1);            // chunk i resident
        __syncthreads();       // visible to all; stage 'wr' drained

        if (i + 2 < NCHUNK) {
            const u32 bw = sb + (u32)wr * BSZ;
#pragma unroll
            for (int sx = 0; sx < 4; sx++)
                if (sd[sx] != 0xFFFFFFFFu)
                    cp16(bw + sd[sx], gx + so[sx] + eoff);
        }
        CP_COMMIT();
        eoff += 32;

        const u32 bb = sb + (u32)cur * BSZ + laneBase;
        const bool last = (i == NCHUNK - 1);

        // ---- p-outer: two 16-t halves, each with its own 16-reg dacc ----
#pragma unroll
        for (int p = 0; p < 2; p++) {
            float dacc[2][2][4];
#pragma unroll
            for (int mt = 0; mt < 2; mt++)
#pragma unroll
                for (int n = 0; n < 2; n++)
#pragma unroll
                    for (int r = 0; r < 4; r++) dacc[mt][n][r] = 0.f;

#pragma unroll
            for (int q = 0; q < 7; q++) {
                u32 b0, b1, b2, b3;
                ldsm_x4t(b0, b1, b2, b3, bb + (u32)q * 1024u + xvo[p]);
                u32 a1[4];
                ldsm_x4(a1[0], a1[1], a1[2], a1[3], a1base + (u32)q * 32u);
                mma16816(dacc[0][0], afr[q], b0, b1);
                mma16816(dacc[0][1], afr[q], b2, b3);
                mma16816(dacc[1][0], a1, b0, b1);
                mma16816(dacc[1][1], a1, b2, b3);
            }

            // fused epilogue for this half (last chunk: only t 0..7 valid)
            const int ntmax = last ? ((p == 0) ? 1 : 0) : 2;
#pragma unroll
            for (int n = 0; n < 2; n++) {
                if (n < ntmax) {
#pragma unroll
                    for (int mt = 0; mt < 2; mt++) {
                        m[2 * mt]     = fmaxf(m[2 * mt],
                                              fmaxf(dacc[mt][n][0], dacc[mt][n][1]));
                        cn[2 * mt]   += (dacc[mt][n][0] > bv[2 * mt])
                                      + (dacc[mt][n][1] > bv[2 * mt]);
                        m[2 * mt + 1] = fmaxf(m[2 * mt + 1],
                                              fmaxf(dacc[mt][n][2], dacc[mt][n][3]));
                        cn[2 * mt + 1] += (dacc[mt][n][2] > bv[2 * mt + 1])
                                        + (dacc[mt][n][3] > bv[2 * mt + 1]);
                    }
                }
            }
        }

        cur = (cur == 2) ? 0 : cur + 1;
        wr  = (wr  == 2) ? 0 : wr  + 1;
    }

    // ---- reduce across the 4 lanes of each quad, write out ----
#pragma unroll
    for (int o = 1; o < 4; o <<= 1) {
#pragma unroll
        for (int r = 0; r < 4; r++) {
            m[r]  = fmaxf(m[r], __shfl_xor_sync(0xffffffffu, m[r], o));
            cn[r] += __shfl_xor_sync(0xffffffffu, cn[r], o);
        }
    }
    if ((lane & 3) == 0) {
        float* ob = out + (size_t)b * 20000 + di * 2000;
#pragma unroll
        for (int r = 0; r < 4; r++) {
            if (jr[r] < 1000) {
                ob[jr[r]]        = m[r];
                ob[1000 + jr[r]] = (float)cn[r] * (1.0f / LSEQ);
            }
        }
    }
}

extern "C" void kernel_launch(void* const* d_in, const int* in_sizes, int n_in,
                              void* d_out, int out_size)
{
    const float* x    = (const float*)d_in[0];  // [16,12,5000]
    const float* W    = (const float*)d_in[1];  // [10,1000,12,9]
    const float* bias = (const float*)d_in[2];  // [10,1000]
    float* out = (float*)d_out;                 // [16,20000]

    dim3 pg((ROWLEN / 2 + 255) / 256, NROWS, 8);
    prep_kernel<<<pg, 256>>>(x);

    cudaFuncSetAttribute(mr_hmma, cudaFuncAttributeMaxDynamicSharedMemorySize, SMEMSZ);
    dim3 grid(8, 16, 10);
    mr_hmma<<<grid, 128, SMEMSZ>>>(W, bias, out);
}

// round 14
// speedup vs baseline: 1.1143x; 1.0125x over previous
#include <cuda_runtime.h>
#include <cuda_fp16.h>
#include <cstdint>
#include <math_constants.h>

// MiniRocket via mma.sync (HMMA) fp16 GEMM, round 14.
// R14 = R13 + (a) packed fp16x2 PPV counting (cvt+hgt2+hadd2, no predicates),
// (b) 6 CTAs/SM: 2-stage ring + persistent A1 (SMEM 29696), launch_bounds(128,6)
// -> 24 warps/SM. Warp tile 32j x 32t, K=112 fp16, 7 ksteps, grid 1280.

#define LSEQ    5000
#define PADX    2112
#define ROWLEN  9224            // PADX + LSEQ + PADX
#define NCH     12
#define NROWS   192             // 16 batch * 12 ch
#define NCHUNK  157             // ceil(5000/32)
#define ASTRIDE 240             // A row stride bytes (112 fp16 + pad), 16 | 240

#define BSZ     7168            // 56 rows x 128B per stage
#define A1OFF   (2 * BSZ)       // 14336: persistent A (mt=1, 64 rows x 240B)
#define SMEMSZ  (A1OFF + 64 * ASTRIDE)   // 29696 -> 6 CTAs/SM

typedef unsigned u32;

// fp16 x, 8 shifted padded copies: g_xh[s*NROWS + row][p] = x[row][p + s - PADX]
__device__ __align__(16) __half g_xh[8 * NROWS * ROWLEN];

// ---------------- prep: padded fp16, 8 shifts ----------------
__global__ void prep_kernel(const float* __restrict__ x) {
    int p2 = blockIdx.x * 256 + threadIdx.x;
    if (p2 >= ROWLEN / 2) return;
    int row = blockIdx.y;                      // 0..191
    int s   = blockIdx.z;                      // 0..7
    int p   = p2 * 2;

    float v0 = 0.f, v1 = 0.f;
    int i0 = p + s - PADX, i1 = i0 + 1;
    if (i0 >= 0 && i0 < LSEQ) v0 = x[(size_t)row * LSEQ + i0];
    if (i1 >= 0 && i1 < LSEQ) v1 = x[(size_t)row * LSEQ + i1];

    __half2 h;
    h.x = __float2half(v0);
    h.y = __float2half(v1);
    *reinterpret_cast<__half2*>(g_xh + ((size_t)s * NROWS + row) * ROWLEN + p) = h;
}

// ---------------- PTX helpers (baseline, sm_80+) ----------------
__device__ __forceinline__ u32 smem_u32(const void* p) {
    u32 a;
    asm("{ .reg .u64 t; cvta.to.shared.u64 t, %1; cvt.u32.u64 %0, t; }"
        : "=r"(a) : "l"(p));
    return a;
}
__device__ __forceinline__ void ldsm_x4(u32& r0, u32& r1, u32& r2, u32& r3, u32 a) {
    asm volatile("ldmatrix.sync.aligned.m8n8.x4.shared.b16 {%0,%1,%2,%3}, [%4];"
                 : "=r"(r0), "=r"(r1), "=r"(r2), "=r"(r3) : "r"(a));
}
__device__ __forceinline__ void ldsm_x4t(u32& r0, u32& r1, u32& r2, u32& r3, u32 a) {
    asm volatile("ldmatrix.sync.aligned.m8n8.x4.trans.shared.b16 {%0,%1,%2,%3}, [%4];"
                 : "=r"(r0), "=r"(r1), "=r"(r2), "=r"(r3) : "r"(a));
}
__device__ __forceinline__ void mma16816(float* d, const u32* a, u32 b0, u32 b1) {
    asm volatile(
        "mma.sync.aligned.m16n8k16.row.col.f32.f16.f16.f32 "
        "{%0,%1,%2,%3}, {%4,%5,%6,%7}, {%8,%9}, {%0,%1,%2,%3};"
        : "+f"(d[0]), "+f"(d[1]), "+f"(d[2]), "+f"(d[3])
        : "r"(a[0]), "r"(a[1]), "r"(a[2]), "r"(a[3]), "r"(b0), "r"(b1));
}
__device__ __forceinline__ void cp16(u32 dst, const void* src) {
    asm volatile("cp.async.cg.shared.global [%0], [%1], 16;"
                 :: "r"(dst), "l"(src) : "memory");
}
#define CP_COMMIT() asm volatile("cp.async.commit_group;" ::: "memory")
#define CP_WAIT(n)  asm volatile("cp.async.wait_group %0;" :: "n"(n) : "memory")

// ---------------- main kernel ----------------
__global__ void __launch_bounds__(128, 6)
mr_hmma(const float* __restrict__ W, const float* __restrict__ bias,
        float* __restrict__ out)
{
    extern __shared__ __align__(1024) char smem[];
    const u32 sb = smem_u32(smem);
    const int tid  = threadIdx.x;
    const int wid  = tid >> 5;      // 0..3
    const int lane = tid & 31;

    const int jt = blockIdx.x;      // 0..7
    const int b  = blockIdx.y;      // 0..15
    const int di = blockIdx.z;      // 0..9
    const int d  = 1 << di;

    // ---- phase 1: stage A mt=0 rows (j&16==0) at slot*ASTRIDE (scratch) ----
    for (int e = tid; e < 64 * 56; e += 128) {
        int slot = e / 56;
        int kk   = (e - slot * 56) * 2;
        int j    = (slot >> 4) * 32 + (slot & 15);
        u32 val = 0;
        int jg = jt * 128 + j;
        if (jg < 1000 && kk < 108) {
            float2 w2 = *reinterpret_cast<const float2*>(
                W + (size_t)(di * 1000 + jg) * 108 + kk);
            __half2 h;
            h.x = __float2half(w2.x);
            h.y = __float2half(w2.y);
            val = *reinterpret_cast<u32*>(&h);
        }
        *reinterpret_cast<u32*>(smem + slot * ASTRIDE + kk * 2) = val;
    }
    __syncthreads();

    // ---- A mt=0 fragments -> registers (7 ksteps x 4 regs = 28) ----
    u32 afr[7][4];
    {
        u32 abase = sb + (u32)(wid * 16 + (lane & 15)) * ASTRIDE
                  + (u32)(lane >> 4) * 16;
#pragma unroll
        for (int q = 0; q < 7; q++)
            ldsm_x4(afr[q][0], afr[q][1], afr[q][2], afr[q][3], abase + q * 32);
    }
    __syncthreads();   // scratch free

    // ---- phase 2: stage A mt=1 rows (j&16) into persistent A1 ----
    for (int e = tid; e < 64 * 56; e += 128) {
        int slot = e / 56;
        int kk   = (e - slot * 56) * 2;
        int j    = (slot >> 4) * 32 + (slot & 15) + 16;
        u32 val = 0;
        int jg = jt * 128 + j;
        if (jg < 1000 && kk < 108) {
            float2 w2 = *reinterpret_cast<const float2*>(
                W + (size_t)(di * 1000 + jg) * 108 + kk);
            __half2 h;
            h.x = __float2half(w2.x);
            h.y = __float2half(w2.y);
            val = *reinterpret_cast<u32*>(&h);
        }
        *reinterpret_cast<u32*>(smem + A1OFF + slot * ASTRIDE + kk * 2) = val;
    }
    const u32 a1base = sb + (u32)A1OFF
                     + (u32)(wid * 16 + (lane & 15)) * ASTRIDE
                     + (u32)(lane >> 4) * 16;

    // ---- staging descriptors: 4 slots/thread (432 valid of 512) ----
    u32 so[4];  // element offset into g_xh (advanced by 32 per chunk)
    u32 sd[4];  // swizzled smem byte offset (~0 = invalid)
#pragma unroll
    for (int sx = 0; sx < 4; sx++) {
        int e = tid + (sx << 7);
        bool valid = e < 108 * 4;
        int s  = valid ? (e >> 2) : 0;
        int ch = e & 3;
        int c = s / 9, k = s - c * 9;
        int o0 = PADX + (k - 4) * d + ch * 8;
        int s8 = o0 & 7, p0 = o0 - s8;
        so[sx] = (u32)((s8 * NROWS + b * NCH + c) * ROWLEN + p0);
        int u = s >> 1, half = s & 1;
        u32 off = (u32)u * 128u + ((u32)((half * 4 + ch) ^ (u & 7)) * 16u);
        sd[sx] = valid ? off : 0xFFFFFFFFu;
    }

    // ---- zero pad slots 108..111 in both stages ----
    if (tid < 32) {
        int st = tid >> 4, idx = tid & 15;
        int s = 108 + (idx >> 2), ch = idx & 3;
        int u = s >> 1, half = s & 1;
        u32 off = (u32)u * 128u + ((u32)((half * 4 + ch) ^ (u & 7)) * 16u);
        *reinterpret_cast<uint4*>(smem + st * BSZ + off) = make_uint4(0, 0, 0, 0);
    }
    __syncthreads();   // A1 + pads written before loop reads/writes stages

    // ---- prologue: async-stage chunk 0 ----
    const __half* gx = g_xh;
#pragma unroll
    for (int sx = 0; sx < 4; sx++)
        if (sd[sx] != 0xFFFFFFFFu) cp16(sb + sd[sx], gx + so[sx]);
    CP_COMMIT();

    // ---- per-lane ldsm-B address components ----
    const u32 laneU    = (u32)((lane & 15) >> 1);
    const u32 laneHalf = (u32)(lane & 1);
    const u32 g0       = (u32)(lane >> 4);
    const u32 laneBase = laneU * 128u;
    u32 xvo[2];
#pragma unroll
    for (int p = 0; p < 2; p++)
        xvo[p] = ((laneHalf * 4u + g0 + 2u * (u32)p) ^ laneU) * 16u;

    // ---- epilogue state: lane owns 4 j rows; counts packed as half2 ----
    const int qd  = lane >> 2;
    const int j0w = jt * 128 + wid * 32;
    float   m[4];
    __half2 bvh[4], cnt2[4];
#pragma unroll
    for (int r = 0; r < 4; r++) {
        int j = j0w + qd + ((r & 1) << 3) + ((r >> 1) << 4);
        float bvv = (j < 1000) ? bias[di * 1000 + j] : 0.0f;
        bvh[r]  = __float2half2_rn(bvv);
        cnt2[r] = __float2half2_rn(0.0f);
        m[r]    = -CUDART_INF_F;
    }

    u32 cs   = 0;        // byte offset of the stage holding chunk i
    u32 eoff = 32;       // element offset of chunk i+1

    for (int i = 0; i < NCHUNK; i++) {
        CP_WAIT(0);            // chunk i resident (only group in flight)
        __syncthreads();       // visible; other stage fully drained

        if (i + 1 < NCHUNK) {
            const u32 bw = sb + (cs ^ (u32)BSZ);
#pragma unroll
            for (int sx = 0; sx < 4; sx++)
                if (sd[sx] != 0xFFFFFFFFu)
                    cp16(bw + sd[sx], gx + so[sx] + eoff);
        }
        CP_COMMIT();
        eoff += 32;

        const u32 bb = sb + cs + laneBase;
        const bool last = (i == NCHUNK - 1);

        // ---- p-outer: two 16-t halves, 16-reg dacc each ----
#pragma unroll
        for (int p = 0; p < 2; p++) {
            float dacc[2][2][4];
#pragma unroll
            for (int mt = 0; mt < 2; mt++)
#pragma unroll
                for (int n = 0; n < 2; n++)
#pragma unroll
                    for (int r = 0; r < 4; r++) dacc[mt][n][r] = 0.f;

#pragma unroll
            for (int q = 0; q < 7; q++) {
                u32 b0, b1, b2, b3;
                ldsm_x4t(b0, b1, b2, b3, bb + (u32)q * 1024u + xvo[p]);
                u32 a1[4];
                ldsm_x4(a1[0], a1[1], a1[2], a1[3], a1base + (u32)q * 32u);
                mma16816(dacc[0][0], afr[q], b0, b1);
                mma16816(dacc[0][1], afr[q], b2, b3);
                mma16816(dacc[1][0], a1, b0, b1);
                mma16816(dacc[1][1], a1, b2, b3);
            }

            // fused epilogue (packed counts); last chunk: only t 0..7 valid
            const int ntmax = last ? ((p == 0) ? 1 : 0) : 2;
#pragma unroll
            for (int n = 0; n < 2; n++) {
                if (n < ntmax) {
#pragma unroll
                    for (int mt = 0; mt < 2; mt++) {
                        const float d0 = dacc[mt][n][0], d1 = dacc[mt][n][1];
                        const float d2 = dacc[mt][n][2], d3 = dacc[mt][n][3];
                        m[2 * mt]     = fmaxf(m[2 * mt],     fmaxf(d0, d1));
                        m[2 * mt + 1] = fmaxf(m[2 * mt + 1], fmaxf(d2, d3));
                        __half2 pk0 = __floats2half2_rn(d0, d1);
                        __half2 pk1 = __floats2half2_rn(d2, d3);
                        cnt2[2 * mt]     = __hadd2(cnt2[2 * mt],
                                                   __hgt2(pk0, bvh[2 * mt]));
                        cnt2[2 * mt + 1] = __hadd2(cnt2[2 * mt + 1],
                                                   __hgt2(pk1, bvh[2 * mt + 1]));
                    }
                }
            }
        }
        cs ^= (u32)BSZ;
    }

    // ---- reduce across the 4 lanes of each quad, write out ----
    float cf[4];
#pragma unroll
    for (int r = 0; r < 4; r++)
        cf[r] = __low2float(cnt2[r]) + __high2float(cnt2[r]);
#pragma unroll
    for (int o = 1; o < 4; o <<= 1) {
#pragma unroll
        for (int r = 0; r < 4; r++) {
            m[r]  = fmaxf(m[r], __shfl_xor_sync(0xffffffffu, m[r], o));
            cf[r] += __shfl_xor_sync(0xffffffffu, cf[r], o);
        }
    }
    if ((lane & 3) == 0) {
        float* ob = out + (size_t)b * 20000 + di * 2000;
#pragma unroll
        for (int r = 0; r < 4; r++) {
            int j = j0w + qd + ((r & 1) << 3) + ((r >> 1) << 4);
            if (j < 1000) {
                ob[j]        = m[r];
                ob[1000 + j] = cf[r] * (1.0f / LSEQ);
            }
        }
    }
}

extern "C" void kernel_launch(void* const* d_in, const int* in_sizes, int n_in,
                              void* d_out, int out_size)
{
    const float* x    = (const float*)d_in[0];  // [16,12,5000]
    const float* W    = (const float*)d_in[1];  // [10,1000,12,9]
    const float* bias = (const float*)d_in[2];  // [10,1000]
    float* out = (float*)d_out;                 // [16,20000]

    dim3 pg((ROWLEN / 2 + 255) / 256, NROWS, 8);
    prep_kernel<<<pg, 256>>>(x);

    cudaFuncSetAttribute(mr_hmma, cudaFuncAttributeMaxDynamicSharedMemorySize, SMEMSZ);
    dim3 grid(8, 16, 10);
    mr_hmma<<<grid, 128, SMEMSZ>>>(W, bias, out);
}

// round 15
// speedup vs baseline: 1.1480x; 1.0303x over previous
#include <cuda_runtime.h>
#include <cuda_fp16.h>
#include <cstdint>
#include <math_constants.h>

// MiniRocket via mma.sync (HMMA) fp16 GEMM, round 15.
// R15 = R14 + t-split 2: 2560 CTAs (each ~78 chunks) to fix CTA-count
// quantization (8.42 CTAs/SM in 2 batches of 6 = 70% util -> 16.84 in 3
// batches = 94%). Cross-CTA combine: atomicMax (order-preserving uint key)
// for max, atomicAdd for PPV counts; init + finalize mini-kernels.

#define LSEQ    5000
#define PADX    2112
#define ROWLEN  9224            // PADX + LSEQ + PADX
#define NCH     12
#define NROWS   192             // 16 batch * 12 ch
#define NCHUNK  157             // ceil(5000/32)
#define SPLIT   78              // tz=0: chunks [0,78); tz=1: chunks [78,157)
#define ASTRIDE 240             // A row stride bytes (112 fp16 + pad), 16 | 240
#define OUTN    (16 * 20000)

#define BSZ     7168            // 56 rows x 128B per stage
#define A1OFF   (2 * BSZ)       // 14336: persistent A (mt=1, 64 rows x 240B)
#define SMEMSZ  (A1OFF + 64 * ASTRIDE)   // 29696 -> 6 CTAs/SM

typedef unsigned u32;

// fp16 x, 8 shifted padded copies: g_xh[s*NROWS + row][p] = x[row][p + s - PADX]
__device__ __align__(16) __half g_xh[8 * NROWS * ROWLEN];

// ---------------- prep: padded fp16, 8 shifts ----------------
__global__ void prep_kernel(const float* __restrict__ x) {
    int p2 = blockIdx.x * 256 + threadIdx.x;
    if (p2 >= ROWLEN / 2) return;
    int row = blockIdx.y;                      // 0..191
    int s   = blockIdx.z;                      // 0..7
    int p   = p2 * 2;

    float v0 = 0.f, v1 = 0.f;
    int i0 = p + s - PADX, i1 = i0 + 1;
    if (i0 >= 0 && i0 < LSEQ) v0 = x[(size_t)row * LSEQ + i0];
    if (i1 >= 0 && i1 < LSEQ) v1 = x[(size_t)row * LSEQ + i1];

    __half2 h;
    h.x = __float2half(v0);
    h.y = __float2half(v1);
    *reinterpret_cast<__half2*>(g_xh + ((size_t)s * NROWS + row) * ROWLEN + p) = h;
}

// ---------------- out init / finalize (atomic combine support) ----------------
// key(f) is an order-preserving map float->uint; all finite keys > 0.
__device__ __forceinline__ u32 fkey(float f) {
    u32 u = __float_as_uint(f);
    return (u & 0x80000000u) ? ~u : (u | 0x80000000u);
}
__global__ void init_kernel(float* out) {
    int i = blockIdx.x * 256 + threadIdx.x;
    if (i < OUTN) reinterpret_cast<u32*>(out)[i] = 0u;   // 0 < key(any finite)
}
__global__ void fin_kernel(float* out) {
    int i = blockIdx.x * 256 + threadIdx.x;
    if (i >= OUTN) return;
    int sub = (i % 20000) % 2000;
    if (sub < 1000) {
        u32 k = reinterpret_cast<u32*>(out)[i];
        out[i] = (k & 0x80000000u) ? __uint_as_float(k & 0x7FFFFFFFu)
                                   : __uint_as_float(~k);
    } else {
        out[i] = out[i] * (1.0f / (float)LSEQ);
    }
}

// ---------------- PTX helpers (baseline, sm_80+) ----------------
__device__ __forceinline__ u32 smem_u32(const void* p) {
    u32 a;
    asm("{ .reg .u64 t; cvta.to.shared.u64 t, %1; cvt.u32.u64 %0, t; }"
        : "=r"(a) : "l"(p));
    return a;
}
__device__ __forceinline__ void ldsm_x4(u32& r0, u32& r1, u32& r2, u32& r3, u32 a) {
    asm volatile("ldmatrix.sync.aligned.m8n8.x4.shared.b16 {%0,%1,%2,%3}, [%4];"
                 : "=r"(r0), "=r"(r1), "=r"(r2), "=r"(r3) : "r"(a));
}
__device__ __forceinline__ void ldsm_x4t(u32& r0, u32& r1, u32& r2, u32& r3, u32 a) {
    asm volatile("ldmatrix.sync.aligned.m8n8.x4.trans.shared.b16 {%0,%1,%2,%3}, [%4];"
                 : "=r"(r0), "=r"(r1), "=r"(r2), "=r"(r3) : "r"(a));
}
__device__ __forceinline__ void mma16816(float* d, const u32* a, u32 b0, u32 b1) {
    asm volatile(
        "mma.sync.aligned.m16n8k16.row.col.f32.f16.f16.f32 "
        "{%0,%1,%2,%3}, {%4,%5,%6,%7}, {%8,%9}, {%0,%1,%2,%3};"
        : "+f"(d[0]), "+f"(d[1]), "+f"(d[2]), "+f"(d[3])
        : "r"(a[0]), "r"(a[1]), "r"(a[2]), "r"(a[3]), "r"(b0), "r"(b1));
}
__device__ __forceinline__ void cp16(u32 dst, const void* src) {
    asm volatile("cp.async.cg.shared.global [%0], [%1], 16;"
                 :: "r"(dst), "l"(src) : "memory");
}
#define CP_COMMIT() asm volatile("cp.async.commit_group;" ::: "memory")
#define CP_WAIT(n)  asm volatile("cp.async.wait_group %0;" :: "n"(n) : "memory")

// ---------------- main kernel ----------------
__global__ void __launch_bounds__(128, 6)
mr_hmma(const float* __restrict__ W, const float* __restrict__ bias,
        float* __restrict__ out)
{
    extern __shared__ __align__(1024) char smem[];
    const u32 sb = smem_u32(smem);
    const int tid  = threadIdx.x;
    const int wid  = tid >> 5;      // 0..3
    const int lane = tid & 31;

    const int jt = blockIdx.x;              // 0..7
    const int b  = blockIdx.y;              // 0..15
    const int di = blockIdx.z >> 1;         // 0..9
    const int tz = blockIdx.z & 1;          // 0..1 (t half)
    const int d  = 1 << di;

    const int ci0 = tz ? SPLIT : 0;         // first chunk
    const int ci1 = tz ? NCHUNK : SPLIT;    // one past last

    // ---- phase 1: stage A mt=0 rows (j&16==0) at slot*ASTRIDE (scratch) ----
    for (int e = tid; e < 64 * 56; e += 128) {
        int slot = e / 56;
        int kk   = (e - slot * 56) * 2;
        int j    = (slot >> 4) * 32 + (slot & 15);
        u32 val = 0;
        int jg = jt * 128 + j;
        if (jg < 1000 && kk < 108) {
            float2 w2 = *reinterpret_cast<const float2*>(
                W + (size_t)(di * 1000 + jg) * 108 + kk);
            __half2 h;
            h.x = __float2half(w2.x);
            h.y = __float2half(w2.y);
            val = *reinterpret_cast<u32*>(&h);
        }
        *reinterpret_cast<u32*>(smem + slot * ASTRIDE + kk * 2) = val;
    }
    __syncthreads();

    // ---- A mt=0 fragments -> registers (7 ksteps x 4 regs = 28) ----
    u32 afr[7][4];
    {
        u32 abase = sb + (u32)(wid * 16 + (lane & 15)) * ASTRIDE
                  + (u32)(lane >> 4) * 16;
#pragma unroll
        for (int q = 0; q < 7; q++)
            ldsm_x4(afr[q][0], afr[q][1], afr[q][2], afr[q][3], abase + q * 32);
    }
    __syncthreads();   // scratch free

    // ---- phase 2: stage A mt=1 rows (j&16) into persistent A1 ----
    for (int e = tid; e < 64 * 56; e += 128) {
        int slot = e / 56;
        int kk   = (e - slot * 56) * 2;
        int j    = (slot >> 4) * 32 + (slot & 15) + 16;
        u32 val = 0;
        int jg = jt * 128 + j;
        if (jg < 1000 && kk < 108) {
            float2 w2 = *reinterpret_cast<const float2*>(
                W + (size_t)(di * 1000 + jg) * 108 + kk);
            __half2 h;
            h.x = __float2half(w2.x);
            h.y = __float2half(w2.y);
            val = *reinterpret_cast<u32*>(&h);
        }
        *reinterpret_cast<u32*>(smem + A1OFF + slot * ASTRIDE + kk * 2) = val;
    }
    const u32 a1base = sb + (u32)A1OFF
                     + (u32)(wid * 16 + (lane & 15)) * ASTRIDE
                     + (u32)(lane >> 4) * 16;

    // ---- staging descriptors: 4 slots/thread (432 valid of 512) ----
    u32 so[4];  // element offset into g_xh (advanced by 32 per chunk)
    u32 sd[4];  // swizzled smem byte offset (~0 = invalid)
#pragma unroll
    for (int sx = 0; sx < 4; sx++) {
        int e = tid + (sx << 7);
        bool valid = e < 108 * 4;
        int s  = valid ? (e >> 2) : 0;
        int ch = e & 3;
        int c = s / 9, k = s - c * 9;
        int o0 = PADX + (k - 4) * d + ch * 8;
        int s8 = o0 & 7, p0 = o0 - s8;
        so[sx] = (u32)((s8 * NROWS + b * NCH + c) * ROWLEN + p0)
               + (u32)ci0 * 32u;
        int u = s >> 1, half = s & 1;
        u32 off = (u32)u * 128u + ((u32)((half * 4 + ch) ^ (u & 7)) * 16u);
        sd[sx] = valid ? off : 0xFFFFFFFFu;
    }

    // ---- zero pad slots 108..111 in both stages ----
    if (tid < 32) {
        int st = tid >> 4, idx = tid & 15;
        int s = 108 + (idx >> 2), ch = idx & 3;
        int u = s >> 1, half = s & 1;
        u32 off = (u32)u * 128u + ((u32)((half * 4 + ch) ^ (u & 7)) * 16u);
        *reinterpret_cast<uint4*>(smem + st * BSZ + off) = make_uint4(0, 0, 0, 0);
    }
    __syncthreads();   // A1 + pads written before loop reads/writes stages

    // ---- prologue: async-stage first chunk ----
    const __half* gx = g_xh;
#pragma unroll
    for (int sx = 0; sx < 4; sx++)
        if (sd[sx] != 0xFFFFFFFFu) cp16(sb + sd[sx], gx + so[sx]);
    CP_COMMIT();

    // ---- per-lane ldsm-B address components ----
    const u32 laneU    = (u32)((lane & 15) >> 1);
    const u32 laneHalf = (u32)(lane & 1);
    const u32 g0       = (u32)(lane >> 4);
    const u32 laneBase = laneU * 128u;
    u32 xvo[2];
#pragma unroll
    for (int p = 0; p < 2; p++)
        xvo[p] = ((laneHalf * 4u + g0 + 2u * (u32)p) ^ laneU) * 16u;

    // ---- epilogue state: lane owns 4 j rows; counts packed as half2 ----
    const int qd  = lane >> 2;
    const int j0w = jt * 128 + wid * 32;
    float   m[4];
    __half2 bvh[4], cnt2[4];
#pragma unroll
    for (int r = 0; r < 4; r++) {
        int j = j0w + qd + ((r & 1) << 3) + ((r >> 1) << 4);
        float bvv = (j < 1000) ? bias[di * 1000 + j] : 0.0f;
        bvh[r]  = __float2half2_rn(bvv);
        cnt2[r] = __float2half2_rn(0.0f);
        m[r]    = -CUDART_INF_F;
    }

    u32 cs   = 0;                    // byte offset of stage holding chunk i
    u32 eoff = (u32)(ci0 + 1) * 32u - (u32)ci0 * 32u + (u32)0;  // rel to so[]
    eoff = 32;                       // so[] already biased by ci0

    for (int i = ci0; i < ci1; i++) {
        CP_WAIT(0);            // chunk i resident (only group in flight)
        __syncthreads();       // visible; other stage fully drained

        if (i + 1 < ci1) {
            const u32 bw = sb + (cs ^ (u32)BSZ);
#pragma unroll
            for (int sx = 0; sx < 4; sx++)
                if (sd[sx] != 0xFFFFFFFFu)
                    cp16(bw + sd[sx], gx + so[sx] + eoff);
        }
        CP_COMMIT();
        eoff += 32;

        const u32 bb = sb + cs + laneBase;
        const bool last = (i == NCHUNK - 1);

        // ---- p-outer: two 16-t halves, 16-reg dacc each ----
#pragma unroll
        for (int p = 0; p < 2; p++) {
            float dacc[2][2][4];
#pragma unroll
            for (int mt = 0; mt < 2; mt++)
#pragma unroll
                for (int n = 0; n < 2; n++)
#pragma unroll
                    for (int r = 0; r < 4; r++) dacc[mt][n][r] = 0.f;

#pragma unroll
            for (int q = 0; q < 7; q++) {
                u32 b0, b1, b2, b3;
                ldsm_x4t(b0, b1, b2, b3, bb + (u32)q * 1024u + xvo[p]);
                u32 a1[4];
                ldsm_x4(a1[0], a1[1], a1[2], a1[3], a1base + (u32)q * 32u);
                mma16816(dacc[0][0], afr[q], b0, b1);
                mma16816(dacc[0][1], afr[q], b2, b3);
                mma16816(dacc[1][0], a1, b0, b1);
                mma16816(dacc[1][1], a1, b2, b3);
            }

            // fused epilogue (packed counts); last chunk: only t 0..7 valid
            const int ntmax = last ? ((p == 0) ? 1 : 0) : 2;
#pragma unroll
            for (int n = 0; n < 2; n++) {
                if (n < ntmax) {
#pragma unroll
                    for (int mt = 0; mt < 2; mt++) {
                        const float d0 = dacc[mt][n][0], d1 = dacc[mt][n][1];
                        const float d2 = dacc[mt][n][2], d3 = dacc[mt][n][3];
                        m[2 * mt]     = fmaxf(m[2 * mt],     fmaxf(d0, d1));
                        m[2 * mt + 1] = fmaxf(m[2 * mt + 1], fmaxf(d2, d3));
                        __half2 pk0 = __floats2half2_rn(d0, d1);
                        __half2 pk1 = __floats2half2_rn(d2, d3);
                        cnt2[2 * mt]     = __hadd2(cnt2[2 * mt],
                                                   __hgt2(pk0, bvh[2 * mt]));
                        cnt2[2 * mt + 1] = __hadd2(cnt2[2 * mt + 1],
                                                   __hgt2(pk1, bvh[2 * mt + 1]));
                    }
                }
            }
        }
        cs ^= (u32)BSZ;
    }

    // ---- reduce across the 4 lanes of each quad; atomic combine ----
    float cf[4];
#pragma unroll
    for (int r = 0; r < 4; r++)
        cf[r] = __low2float(cnt2[r]) + __high2float(cnt2[r]);
#pragma unroll
    for (int o = 1; o < 4; o <<= 1) {
#pragma unroll
        for (int r = 0; r < 4; r++) {
            m[r]  = fmaxf(m[r], __shfl_xor_sync(0xffffffffu, m[r], o));
            cf[r] += __shfl_xor_sync(0xffffffffu, cf[r], o);
        }
    }
    if ((lane & 3) == 0) {
        float* ob = out + (size_t)b * 20000 + di * 2000;
#pragma unroll
        for (int r = 0; r < 4; r++) {
            int j = j0w + qd + ((r & 1) << 3) + ((r >> 1) << 4);
            if (j < 1000) {
                atomicMax(reinterpret_cast<u32*>(ob + j), fkey(m[r]));
                atomicAdd(ob + 1000 + j, cf[r]);
            }
        }
    }
}

extern "C" void kernel_launch(void* const* d_in, const int* in_sizes, int n_in,
                              void* d_out, int out_size)
{
    const float* x    = (const float*)d_in[0];  // [16,12,5000]
    const float* W    = (const float*)d_in[1];  // [10,1000,12,9]
    const float* bias = (const float*)d_in[2];  // [10,1000]
    float* out = (float*)d_out;                 // [16,20000]

    dim3 pg((ROWLEN / 2 + 255) / 256, NROWS, 8);
    prep_kernel<<<pg, 256>>>(x);

    init_kernel<<<(OUTN + 255) / 256, 256>>>(out);

    cudaFuncSetAttribute(mr_hmma, cudaFuncAttributeMaxDynamicSharedMemorySize, SMEMSZ);
    dim3 grid(8, 16, 20);                       // z = di*2 + tz
    mr_hmma<<<grid, 128, SMEMSZ>>>(W, bias, out);

    fin_kernel<<<(OUTN + 255) / 256, 256>>>(out);
}